// round 1
// baseline (speedup 1.0000x reference)
#include <cuda_runtime.h>
#include <cuda_bf16.h>
#include <cstdint>

#define N_NODES 50000
#define N_EDGES 600000
#define N_GRAPHS 2048
#define EMB 128
#define N_LAYERS 3
#define ATOM_FEATS 9
#define ATOM_VOCAB 100
#define BOND_FEATS 3
#define BOND_VOCAB 8
#define BOND_DIM 3

// -------- scratch (static device globals; no allocs allowed) --------
__device__ float  g_h[N_NODES * EMB];            // 25.6 MB
__device__ float  g_Y[N_NODES * 3 * EMB];        // 76.8 MB  (Y[n][k*128+j])
__device__ float  g_agg[N_NODES * EMB];          // 25.6 MB
__device__ float4 g_ew[N_LAYERS * N_EDGES];      // 28.8 MB  (xyz = per-k edge weight)
__device__ float  g_gsum[N_GRAPHS * EMB];        // 1 MB
__device__ float  g_gcnt[N_GRAPHS];

// -------- atom encoder: h[n,t] = sum_c atom_emb[c, x[n,c], t] --------
__global__ void k_atom(const int* __restrict__ x, const float* __restrict__ aemb,
                       float* __restrict__ h) {
    int n = blockIdx.x;
    int t = threadIdx.x;
    __shared__ int xi[ATOM_FEATS];
    if (t < ATOM_FEATS) xi[t] = x[n * ATOM_FEATS + t];
    __syncthreads();
    float s = 0.f;
#pragma unroll
    for (int c = 0; c < ATOM_FEATS; c++)
        s += aemb[((size_t)(c * ATOM_VOCAB + xi[c])) * EMB + t];
    h[(size_t)n * EMB + t] = s;
}

// -------- bond encoder for all layers: ew[l][e] = sum_c bond_emb[l,c,ea[e,c],:] --------
__global__ void k_bond(const int* __restrict__ ea, const float* __restrict__ bemb,
                       float4* __restrict__ ew) {
    int e = blockIdx.x * blockDim.x + threadIdx.x;
    if (e >= N_EDGES) return;
    int a0 = ea[e * 3 + 0], a1 = ea[e * 3 + 1], a2 = ea[e * 3 + 2];
#pragma unroll
    for (int l = 0; l < N_LAYERS; l++) {
        const float* b0 = bemb + (((l * BOND_FEATS + 0) * BOND_VOCAB + a0) * BOND_DIM);
        const float* b1 = bemb + (((l * BOND_FEATS + 1) * BOND_VOCAB + a1) * BOND_DIM);
        const float* b2 = bemb + (((l * BOND_FEATS + 2) * BOND_VOCAB + a2) * BOND_DIM);
        float4 w;
        w.x = b0[0] + b1[0] + b2[0];
        w.y = b0[1] + b1[1] + b2[1];
        w.z = b0[2] + b1[2] + b2[2];
        w.w = 0.f;
        ew[(size_t)l * N_EDGES + e] = w;
    }
}

// -------- GEMM: Y[M,384] = h[M,128] @ B, B(i, k*128+j) = Wl[k][i][j] --------
#define BM 64
#define BN 64
#define BK 32
__global__ void k_gemm(const float* __restrict__ A, const float* __restrict__ Wl,
                       float* __restrict__ Y, int M) {
    __shared__ float As[BK][BM + 4];
    __shared__ float Bs[BK][BN];
    int tid = threadIdx.x;               // 256 threads
    int tx = tid & 15, ty = tid >> 4;    // 16 x 16
    int m0 = blockIdx.y * BM;
    int n0 = blockIdx.x * BN;            // 0..320, each tile inside one k-slot
    int kslot = n0 >> 7;
    int j0 = n0 & 127;
    const float* B = Wl + (size_t)kslot * EMB * EMB + j0;  // B(i,j') = B[i*128+j']

    float acc[4][4];
#pragma unroll
    for (int i = 0; i < 4; i++)
#pragma unroll
        for (int j = 0; j < 4; j++) acc[i][j] = 0.f;

    for (int kk0 = 0; kk0 < EMB; kk0 += BK) {
        // A tile: 64x32 = 512 float4
#pragma unroll
        for (int r = 0; r < 2; r++) {
            int lin = tid + r * 256;
            int row = lin >> 3;
            int col4 = (lin & 7) << 2;
            float4 v = make_float4(0.f, 0.f, 0.f, 0.f);
            int gm = m0 + row;
            if (gm < M) v = *(const float4*)(A + (size_t)gm * EMB + kk0 + col4);
            As[col4 + 0][row] = v.x;
            As[col4 + 1][row] = v.y;
            As[col4 + 2][row] = v.z;
            As[col4 + 3][row] = v.w;
        }
        // B tile: 32x64 = 512 float4
#pragma unroll
        for (int r = 0; r < 2; r++) {
            int lin = tid + r * 256;
            int row = lin >> 4;
            int col4 = (lin & 15) << 2;
            *(float4*)&Bs[row][col4] =
                *(const float4*)(B + (size_t)(kk0 + row) * EMB + col4);
        }
        __syncthreads();
#pragma unroll
        for (int kk = 0; kk < BK; kk++) {
            float a[4], bb[4];
#pragma unroll
            for (int i = 0; i < 4; i++) a[i] = As[kk][ty * 4 + i];
#pragma unroll
            for (int j = 0; j < 4; j++) bb[j] = Bs[kk][tx * 4 + j];
#pragma unroll
            for (int i = 0; i < 4; i++)
#pragma unroll
                for (int j = 0; j < 4; j++) acc[i][j] += a[i] * bb[j];
        }
        __syncthreads();
    }
#pragma unroll
    for (int i = 0; i < 4; i++) {
        int gm = m0 + ty * 4 + i;
        if (gm >= M) continue;
        float* yrow = Y + (size_t)gm * (3 * EMB) + n0 + tx * 4;
#pragma unroll
        for (int j = 0; j < 4; j++) yrow[j] = acc[i][j];
    }
}

// -------- edge scatter: agg[dst] += sum_k ew[k] * Y[src, k, :]; 1 warp/edge --------
__global__ void k_scatter(const int* __restrict__ ei, const float4* __restrict__ ew,
                          const float* __restrict__ Y, float* __restrict__ agg) {
    int e = blockIdx.x * (blockDim.x >> 5) + (threadIdx.x >> 5);
    if (e >= N_EDGES) return;
    int lane = threadIdx.x & 31;
    int src = __ldg(&ei[e]);
    int dst = __ldg(&ei[N_EDGES + e]);
    float4 w = __ldg(&ew[e]);
    const float* y = Y + (size_t)src * (3 * EMB) + lane * 4;
    float4 y0 = *(const float4*)(y);
    float4 y1 = *(const float4*)(y + EMB);
    float4 y2 = *(const float4*)(y + 2 * EMB);
    float4 v;
    v.x = w.x * y0.x + w.y * y1.x + w.z * y2.x;
    v.y = w.x * y0.y + w.y * y1.y + w.z * y2.y;
    v.z = w.x * y0.z + w.y * y1.z + w.z * y2.z;
    v.w = w.x * y0.w + w.y * y1.w + w.z * y2.w;
    float* a = agg + (size_t)dst * EMB + lane * 4;
    asm volatile("red.global.add.v4.f32 [%0], {%1, %2, %3, %4};"
                 :: "l"(a), "f"(v.x), "f"(v.y), "f"(v.z), "f"(v.w)
                 : "memory");
}

// -------- update: h = act(agg + sum_k b[layer,k]) + h --------
__global__ void k_update(const float* __restrict__ agg, const float* __restrict__ bl,
                         float* __restrict__ h, int relu) {
    int n = blockIdx.x;
    int t = threadIdx.x;
    float bs = bl[t] + bl[EMB + t] + bl[2 * EMB + t];
    size_t idx = (size_t)n * EMB + t;
    float v = agg[idx] + bs;
    if (relu) v = fmaxf(v, 0.f);
    h[idx] = v + h[idx];
}

// -------- pooling --------
__global__ void k_pool(const int* __restrict__ batch, const float* __restrict__ h,
                       float* __restrict__ gsum, float* __restrict__ gcnt) {
    int n = blockIdx.x;
    int t = threadIdx.x;
    int g = __ldg(&batch[n]);
    atomicAdd(&gsum[(size_t)g * EMB + t], h[(size_t)n * EMB + t]);
    if (t == 0) atomicAdd(&gcnt[g], 1.0f);
}

// -------- final FCs: out[g] = (hg @ fc1 + b1) @ fc2 + b2 --------
__global__ void k_final(const float* __restrict__ gsum, const float* __restrict__ gcnt,
                        const float* __restrict__ fc1_w, const float* __restrict__ fc1_b,
                        const float* __restrict__ fc2_w, const float* __restrict__ fc2_b,
                        float* __restrict__ out) {
    int g = blockIdx.x;
    int t = threadIdx.x;
    __shared__ float hg[EMB];
    __shared__ float red[EMB];
    float cnt = fmaxf(gcnt[g], 1.0f);
    hg[t] = gsum[(size_t)g * EMB + t] / cnt;
    __syncthreads();
    float z = fc1_b[t];
#pragma unroll 8
    for (int i = 0; i < EMB; i++) z += hg[i] * fc1_w[i * EMB + t];
    red[t] = z * fc2_w[t];
    __syncthreads();
    for (int s = 64; s > 0; s >>= 1) {
        if (t < s) red[t] += red[t + s];
        __syncthreads();
    }
    if (t == 0) out[g] = red[0] + fc2_b[0];
}

extern "C" void kernel_launch(void* const* d_in, const int* in_sizes, int n_in,
                              void* d_out, int out_size) {
    const int*   x     = (const int*)d_in[0];
    const int*   ei    = (const int*)d_in[1];
    const int*   ea    = (const int*)d_in[2];
    const int*   batch = (const int*)d_in[3];
    const float* aemb  = (const float*)d_in[4];
    const float* bemb  = (const float*)d_in[5];
    const float* W     = (const float*)d_in[6];
    const float* b     = (const float*)d_in[7];
    const float* fc1_w = (const float*)d_in[8];
    const float* fc1_b = (const float*)d_in[9];
    const float* fc2_w = (const float*)d_in[10];
    const float* fc2_b = (const float*)d_in[11];
    float* out = (float*)d_out;

    float *h, *Y, *agg, *gsum, *gcnt;
    float4* ew;
    cudaGetSymbolAddress((void**)&h, g_h);
    cudaGetSymbolAddress((void**)&Y, g_Y);
    cudaGetSymbolAddress((void**)&agg, g_agg);
    cudaGetSymbolAddress((void**)&ew, g_ew);
    cudaGetSymbolAddress((void**)&gsum, g_gsum);
    cudaGetSymbolAddress((void**)&gcnt, g_gcnt);

    k_atom<<<N_NODES, EMB>>>(x, aemb, h);
    k_bond<<<(N_EDGES + 255) / 256, 256>>>(ea, bemb, ew);

    for (int layer = 0; layer < N_LAYERS; layer++) {
        cudaMemsetAsync(agg, 0, (size_t)N_NODES * EMB * sizeof(float));
        dim3 gg(3 * EMB / BN, (N_NODES + BM - 1) / BM);
        k_gemm<<<gg, 256>>>(h, W + (size_t)layer * BOND_DIM * EMB * EMB, Y, N_NODES);
        k_scatter<<<(N_EDGES + 7) / 8, 256>>>(ei, ew + (size_t)layer * N_EDGES, Y, agg);
        k_update<<<N_NODES, EMB>>>(agg, b + (size_t)layer * BOND_DIM * EMB, h,
                                   layer < N_LAYERS - 1 ? 1 : 0);
    }

    cudaMemsetAsync(gsum, 0, (size_t)N_GRAPHS * EMB * sizeof(float));
    cudaMemsetAsync(gcnt, 0, (size_t)N_GRAPHS * sizeof(float));
    k_pool<<<N_NODES, EMB>>>(batch, h, gsum, gcnt);
    k_final<<<N_GRAPHS, EMB>>>(gsum, gcnt, fc1_w, fc1_b, fc2_w, fc2_b, out);
}

// round 3
// speedup vs baseline: 1.7299x; 1.7299x over previous
#include <cuda_runtime.h>
#include <cuda_fp16.h>
#include <cuda_bf16.h>
#include <cstdint>

#define N_NODES 50000
#define N_EDGES 600000
#define N_GRAPHS 2048
#define EMB 128
#define N_LAYERS 3
#define ATOM_FEATS 9
#define ATOM_VOCAB 100
#define BOND_FEATS 3
#define BOND_VOCAB 8
#define BOND_DIM 3

// ---------------- scratch ----------------
__device__ float  g_h[N_NODES * EMB];             // fp32 master h
__device__ __half g_hh[N_NODES * EMB];            // fp16 copy for MMA
__device__ __half g_Y[(size_t)N_NODES * 3 * EMB]; // fp16 messages, 38.4MB
__device__ float  g_agg[N_NODES * EMB];
__device__ float4 g_ew[N_LAYERS * N_EDGES];
__device__ __half g_WT[N_LAYERS * 3 * EMB * EMB]; // WT[l][n=ks*128+j][i] = W[l][ks][i][j]
__device__ float  g_gsum[N_GRAPHS * EMB];
__device__ float  g_gcnt[N_GRAPHS];

__device__ __forceinline__ uint32_t smem_u32(const void* p) {
    uint32_t a;
    asm("{ .reg .u64 t; cvta.to.shared.u64 t, %1; cvt.u32.u64 %0, t; }" : "=r"(a) : "l"(p));
    return a;
}

// ---------------- atom encoder ----------------
__global__ void k_atom(const int* __restrict__ x, const float* __restrict__ aemb,
                       float* __restrict__ h, __half* __restrict__ hh) {
    int n = blockIdx.x;
    int t = threadIdx.x;
    __shared__ int xi[ATOM_FEATS];
    if (t < ATOM_FEATS) xi[t] = x[n * ATOM_FEATS + t];
    __syncthreads();
    float s = 0.f;
#pragma unroll
    for (int c = 0; c < ATOM_FEATS; c++)
        s += aemb[((size_t)(c * ATOM_VOCAB + xi[c])) * EMB + t];
    size_t idx = (size_t)n * EMB + t;
    h[idx] = s;
    hh[idx] = __float2half(s);
}

// ---------------- bond encoder (all layers) ----------------
__global__ void k_bond(const int* __restrict__ ea, const float* __restrict__ bemb,
                       float4* __restrict__ ew) {
    int e = blockIdx.x * blockDim.x + threadIdx.x;
    if (e >= N_EDGES) return;
    int a0 = ea[e * 3 + 0], a1 = ea[e * 3 + 1], a2 = ea[e * 3 + 2];
#pragma unroll
    for (int l = 0; l < N_LAYERS; l++) {
        const float* b0 = bemb + (((l * BOND_FEATS + 0) * BOND_VOCAB + a0) * BOND_DIM);
        const float* b1 = bemb + (((l * BOND_FEATS + 1) * BOND_VOCAB + a1) * BOND_DIM);
        const float* b2 = bemb + (((l * BOND_FEATS + 2) * BOND_VOCAB + a2) * BOND_DIM);
        float4 w;
        w.x = b0[0] + b1[0] + b2[0];
        w.y = b0[1] + b1[1] + b2[1];
        w.z = b0[2] + b1[2] + b2[2];
        w.w = 0.f;
        ew[(size_t)l * N_EDGES + e] = w;
    }
}

// ---------------- W -> fp16 transposed ----------------
__global__ void k_prepW(const float* __restrict__ W, __half* __restrict__ WT) {
    int bl = blockIdx.x;                 // l*384 + n
    int l = bl / (3 * EMB), n = bl % (3 * EMB);
    int ks = n >> 7, j = n & 127;
    int i = threadIdx.x;
    WT[((size_t)l * 3 * EMB + n) * EMB + i] =
        __float2half(W[(((size_t)l * BOND_DIM + ks) * EMB + i) * EMB + j]);
}

// ---------------- HMMA GEMM: Y[m,n] = sum_i hh[m,i] * WT[n,i] ----------------
// Block tile 128(M) x 64(N), 8 warps (4 m x 2 n), warp tile 32x32, K=128 resident.
#define LDA 136   // padded row stride in halves (272B; conflict-free ldmatrix)
#define GBM 128
#define GBN 64

__global__ void __launch_bounds__(256, 2)
k_gemm_mma(const __half* __restrict__ hh, const __half* __restrict__ WT,
           __half* __restrict__ Y) {
    extern __shared__ __half sm[];
    __half* As = sm;               // [128][LDA]
    __half* Bs = sm + GBM * LDA;   // [64][LDA]
    const int M = N_NODES;
    int tid = threadIdx.x;
    int m0 = blockIdx.y * GBM;
    int n0 = blockIdx.x * GBN;

    // Load A tile (128 rows x 128 halves): 2048 uint4 chunks, 8 per thread
#pragma unroll
    for (int r = 0; r < 8; r++) {
        int lin = tid + r * 256;
        int row = lin >> 4;
        int col = (lin & 15) << 3;
        uint4 v = make_uint4(0u, 0u, 0u, 0u);
        int gm = m0 + row;
        if (gm < M) v = *(const uint4*)(hh + (size_t)gm * EMB + col);
        *(uint4*)(As + row * LDA + col) = v;
    }
    // Load B tile (64 rows x 128 halves): 1024 chunks, 4 per thread
#pragma unroll
    for (int r = 0; r < 4; r++) {
        int lin = tid + r * 256;
        int row = lin >> 4;
        int col = (lin & 15) << 3;
        uint4 v = *(const uint4*)(WT + (size_t)(n0 + row) * EMB + col);
        *(uint4*)(Bs + row * LDA + col) = v;
    }
    __syncthreads();

    int wid = tid >> 5, lane = tid & 31;
    int wm = wid & 3, wn = wid >> 2;       // warp position: 4 x 2
    int mbase = wm * 32, nbase = wn * 32;

    float acc[2][4][4];
#pragma unroll
    for (int i = 0; i < 2; i++)
#pragma unroll
        for (int j = 0; j < 4; j++)
#pragma unroll
            for (int q = 0; q < 4; q++) acc[i][j][q] = 0.f;

#pragma unroll
    for (int k16 = 0; k16 < 8; k16++) {
        int kc = k16 * 16;
        // A fragments: 2 x m16k16
        uint32_t a[2][4];
#pragma unroll
        for (int i = 0; i < 2; i++) {
            int row = mbase + i * 16 + (lane & 15);
            int col = kc + (lane >> 4) * 8;
            uint32_t addr = smem_u32(As + row * LDA + col);
            asm volatile("ldmatrix.sync.aligned.m8n8.x4.shared.b16 {%0,%1,%2,%3}, [%4];"
                         : "=r"(a[i][0]), "=r"(a[i][1]), "=r"(a[i][2]), "=r"(a[i][3])
                         : "r"(addr));
        }
        // B fragments: 2 x (n16 x k16) -> 4 n8 tiles
        uint32_t bf[2][4];
#pragma unroll
        for (int j = 0; j < 2; j++) {
            int nrow = nbase + j * 16 + ((lane >> 4) << 3) + (lane & 7);
            int col = kc + (((lane >> 3) & 1) << 3);
            uint32_t addr = smem_u32(Bs + nrow * LDA + col);
            asm volatile("ldmatrix.sync.aligned.m8n8.x4.shared.b16 {%0,%1,%2,%3}, [%4];"
                         : "=r"(bf[j][0]), "=r"(bf[j][1]), "=r"(bf[j][2]), "=r"(bf[j][3])
                         : "r"(addr));
        }
#pragma unroll
        for (int i = 0; i < 2; i++) {
#pragma unroll
            for (int jj = 0; jj < 4; jj++) {
                uint32_t b0 = bf[jj >> 1][(jj & 1) * 2 + 0];
                uint32_t b1 = bf[jj >> 1][(jj & 1) * 2 + 1];
                asm volatile(
                    "mma.sync.aligned.m16n8k16.row.col.f32.f16.f16.f32 "
                    "{%0,%1,%2,%3}, {%4,%5,%6,%7}, {%8,%9}, {%0,%1,%2,%3};"
                    : "+f"(acc[i][jj][0]), "+f"(acc[i][jj][1]),
                      "+f"(acc[i][jj][2]), "+f"(acc[i][jj][3])
                    : "r"(a[i][0]), "r"(a[i][1]), "r"(a[i][2]), "r"(a[i][3]),
                      "r"(b0), "r"(b1));
            }
        }
    }

    // Store C as fp16 (Y stride = 384)
#pragma unroll
    for (int i = 0; i < 2; i++) {
        int row0 = m0 + mbase + i * 16 + (lane >> 2);
#pragma unroll
        for (int jj = 0; jj < 4; jj++) {
            int col = n0 + nbase + jj * 8 + 2 * (lane & 3);
            if (row0 < M) {
                half2 v = __floats2half2_rn(acc[i][jj][0], acc[i][jj][1]);
                *(half2*)(Y + (size_t)row0 * (3 * EMB) + col) = v;
            }
            if (row0 + 8 < M) {
                half2 v = __floats2half2_rn(acc[i][jj][2], acc[i][jj][3]);
                *(half2*)(Y + (size_t)(row0 + 8) * (3 * EMB) + col) = v;
            }
        }
    }
}

// ---------------- edge scatter: agg[dst] += sum_k ew[k] * Y[src,k,:] ----------------
__global__ void k_scatter(const int* __restrict__ ei, const float4* __restrict__ ew,
                          const __half* __restrict__ Y, float* __restrict__ agg) {
    int e = blockIdx.x * (blockDim.x >> 5) + (threadIdx.x >> 5);
    if (e >= N_EDGES) return;
    int lane = threadIdx.x & 31;
    int src = __ldg(&ei[e]);
    int dst = __ldg(&ei[N_EDGES + e]);
    float4 w = __ldg(&ew[e]);
    const __half* y = Y + (size_t)src * (3 * EMB) + lane * 4;
    uint2 u0 = __ldg((const uint2*)(y));
    uint2 u1 = __ldg((const uint2*)(y + EMB));
    uint2 u2 = __ldg((const uint2*)(y + 2 * EMB));
    float2 a0 = __half22float2(*(const half2*)&u0.x), a1 = __half22float2(*(const half2*)&u0.y);
    float2 b0 = __half22float2(*(const half2*)&u1.x), b1 = __half22float2(*(const half2*)&u1.y);
    float2 c0 = __half22float2(*(const half2*)&u2.x), c1 = __half22float2(*(const half2*)&u2.y);
    float4 v;
    v.x = w.x * a0.x + w.y * b0.x + w.z * c0.x;
    v.y = w.x * a0.y + w.y * b0.y + w.z * c0.y;
    v.z = w.x * a1.x + w.y * b1.x + w.z * c1.x;
    v.w = w.x * a1.y + w.y * b1.y + w.z * c1.y;
    float* a = agg + (size_t)dst * EMB + lane * 4;
    asm volatile("red.global.add.v4.f32 [%0], {%1, %2, %3, %4};"
                 :: "l"(a), "f"(v.x), "f"(v.y), "f"(v.z), "f"(v.w)
                 : "memory");
}

// ---------------- update ----------------
__global__ void k_update(const float* __restrict__ agg, const float* __restrict__ bl,
                         float* __restrict__ h, __half* __restrict__ hh, int relu) {
    int n = blockIdx.x;
    int t = threadIdx.x;
    float bs = bl[t] + bl[EMB + t] + bl[2 * EMB + t];
    size_t idx = (size_t)n * EMB + t;
    float v = agg[idx] + bs;
    if (relu) v = fmaxf(v, 0.f);
    float nv = v + h[idx];
    h[idx] = nv;
    hh[idx] = __float2half(nv);
}

// ---------------- pooling ----------------
__global__ void k_pool(const int* __restrict__ batch, const float* __restrict__ h,
                       float* __restrict__ gsum, float* __restrict__ gcnt) {
    int n = blockIdx.x;
    int t = threadIdx.x;
    int g = __ldg(&batch[n]);
    atomicAdd(&gsum[(size_t)g * EMB + t], h[(size_t)n * EMB + t]);
    if (t == 0) atomicAdd(&gcnt[g], 1.0f);
}

// ---------------- final FCs ----------------
__global__ void k_final(const float* __restrict__ gsum, const float* __restrict__ gcnt,
                        const float* __restrict__ fc1_w, const float* __restrict__ fc1_b,
                        const float* __restrict__ fc2_w, const float* __restrict__ fc2_b,
                        float* __restrict__ out) {
    int g = blockIdx.x;
    int t = threadIdx.x;
    __shared__ float hg[EMB];
    __shared__ float red[EMB];
    float cnt = fmaxf(gcnt[g], 1.0f);
    hg[t] = gsum[(size_t)g * EMB + t] / cnt;
    __syncthreads();
    float z = fc1_b[t];
#pragma unroll 8
    for (int i = 0; i < EMB; i++) z += hg[i] * fc1_w[i * EMB + t];
    red[t] = z * fc2_w[t];
    __syncthreads();
    for (int s = 64; s > 0; s >>= 1) {
        if (t < s) red[t] += red[t + s];
        __syncthreads();
    }
    if (t == 0) out[g] = red[0] + fc2_b[0];
}

extern "C" void kernel_launch(void* const* d_in, const int* in_sizes, int n_in,
                              void* d_out, int out_size) {
    const int*   x     = (const int*)d_in[0];
    const int*   ei    = (const int*)d_in[1];
    const int*   ea    = (const int*)d_in[2];
    const int*   batch = (const int*)d_in[3];
    const float* aemb  = (const float*)d_in[4];
    const float* bemb  = (const float*)d_in[5];
    const float* W     = (const float*)d_in[6];
    const float* b     = (const float*)d_in[7];
    const float* fc1_w = (const float*)d_in[8];
    const float* fc1_b = (const float*)d_in[9];
    const float* fc2_w = (const float*)d_in[10];
    const float* fc2_b = (const float*)d_in[11];
    float* out = (float*)d_out;

    float *h, *agg, *gsum, *gcnt;
    __half *hh, *Y, *WT;
    float4* ew;
    cudaGetSymbolAddress((void**)&h, g_h);
    cudaGetSymbolAddress((void**)&hh, g_hh);
    cudaGetSymbolAddress((void**)&Y, g_Y);
    cudaGetSymbolAddress((void**)&agg, g_agg);
    cudaGetSymbolAddress((void**)&ew, g_ew);
    cudaGetSymbolAddress((void**)&WT, g_WT);
    cudaGetSymbolAddress((void**)&gsum, g_gsum);
    cudaGetSymbolAddress((void**)&gcnt, g_gcnt);

    const int smem_bytes = (GBM + GBN) * LDA * sizeof(__half);   // 52224
    cudaFuncSetAttribute(k_gemm_mma, cudaFuncAttributeMaxDynamicSharedMemorySize, smem_bytes);

    k_atom<<<N_NODES, EMB>>>(x, aemb, h, hh);
    k_bond<<<(N_EDGES + 255) / 256, 256>>>(ea, bemb, ew);
    k_prepW<<<N_LAYERS * 3 * EMB, EMB>>>(W, WT);

    for (int layer = 0; layer < N_LAYERS; layer++) {
        cudaMemsetAsync(agg, 0, (size_t)N_NODES * EMB * sizeof(float));
        dim3 gg(3 * EMB / GBN, (N_NODES + GBM - 1) / GBM);
        k_gemm_mma<<<gg, 256, smem_bytes>>>(hh, WT + (size_t)layer * 3 * EMB * EMB, Y);
        k_scatter<<<(N_EDGES + 7) / 8, 256>>>(ei, ew + (size_t)layer * N_EDGES, Y, agg);
        k_update<<<N_NODES, EMB>>>(agg, b + (size_t)layer * BOND_DIM * EMB, h, hh,
                                   layer < N_LAYERS - 1 ? 1 : 0);
    }

    cudaMemsetAsync(gsum, 0, (size_t)N_GRAPHS * EMB * sizeof(float));
    cudaMemsetAsync(gcnt, 0, (size_t)N_GRAPHS * sizeof(float));
    k_pool<<<N_NODES, EMB>>>(batch, h, gsum, gcnt);
    k_final<<<N_GRAPHS, EMB>>>(gsum, gcnt, fc1_w, fc1_b, fc2_w, fc2_b, out);
}

// round 4
// speedup vs baseline: 2.0596x; 1.1906x over previous
#include <cuda_runtime.h>
#include <cuda_fp16.h>
#include <cuda_bf16.h>
#include <cstdint>

#define N_NODES 50000
#define N_EDGES 600000
#define N_GRAPHS 2048
#define EMB 128
#define N_LAYERS 3
#define ATOM_FEATS 9
#define ATOM_VOCAB 100
#define BOND_FEATS 3
#define BOND_VOCAB 8
#define BOND_DIM 3

// ---------------- scratch ----------------
__device__ float  g_h[N_NODES * EMB];              // fp32 master h
__device__ __half g_hh[N_NODES * EMB];             // fp16 copy for gather/MMA
__device__ __half g_Z[(size_t)N_NODES * 3 * EMB];  // fp16 aggregated features
__device__ float4 g_ewc[N_LAYERS * N_EDGES];       // edge weights in CSR order
__device__ __half g_WT[N_LAYERS * EMB * 3 * EMB];  // WT[l][j][k*128+i] = W[l][k][i][j]
__device__ float  g_gsum[N_GRAPHS * EMB];
__device__ float  g_gcnt[N_GRAPHS];
// CSR
__device__ int    g_cnt[N_NODES];
__device__ int    g_start[N_NODES + 1];
__device__ int    g_cursor[N_NODES];
__device__ int    g_csr_src[N_EDGES];
__device__ int    g_pos[N_EDGES];

__device__ __forceinline__ uint32_t smem_u32(const void* p) {
    uint32_t a;
    asm("{ .reg .u64 t; cvta.to.shared.u64 t, %1; cvt.u32.u64 %0, t; }" : "=r"(a) : "l"(p));
    return a;
}

// ---------------- atom encoder ----------------
__global__ void k_atom(const int* __restrict__ x, const float* __restrict__ aemb,
                       float* __restrict__ h, __half* __restrict__ hh) {
    int n = blockIdx.x;
    int t = threadIdx.x;
    __shared__ int xi[ATOM_FEATS];
    if (t < ATOM_FEATS) xi[t] = x[n * ATOM_FEATS + t];
    __syncthreads();
    float s = 0.f;
#pragma unroll
    for (int c = 0; c < ATOM_FEATS; c++)
        s += aemb[((size_t)(c * ATOM_VOCAB + xi[c])) * EMB + t];
    size_t idx = (size_t)n * EMB + t;
    h[idx] = s;
    hh[idx] = __float2half(s);
}

// ---------------- CSR build ----------------
__global__ void k_count(const int* __restrict__ ei, int* __restrict__ cnt) {
    int e = blockIdx.x * blockDim.x + threadIdx.x;
    if (e < N_EDGES) atomicAdd(&cnt[ei[N_EDGES + e]], 1);
}

__global__ void k_scan(const int* __restrict__ cnt, int* __restrict__ start,
                       int* __restrict__ cursor) {
    __shared__ int ssum[1024];
    int t = threadIdx.x;
    const int PER = 49;   // 1024*49 = 50176 >= 50000
    int lo = t * PER;
    int s = 0;
    for (int i = 0; i < PER; i++) {
        int idx = lo + i;
        if (idx < N_NODES) s += cnt[idx];
    }
    ssum[t] = s;
    __syncthreads();
    for (int off = 1; off < 1024; off <<= 1) {
        int v = (t >= off) ? ssum[t - off] : 0;
        __syncthreads();
        ssum[t] += v;
        __syncthreads();
    }
    int run = ssum[t] - s;   // exclusive prefix
    for (int i = 0; i < PER; i++) {
        int idx = lo + i;
        if (idx < N_NODES) {
            start[idx] = run;
            cursor[idx] = run;
            run += cnt[idx];
        }
    }
    if (t == 0) start[N_NODES] = N_EDGES;
}

__global__ void k_place(const int* __restrict__ ei, int* __restrict__ cursor,
                        int* __restrict__ csr_src, int* __restrict__ pos) {
    int e = blockIdx.x * blockDim.x + threadIdx.x;
    if (e >= N_EDGES) return;
    int d = ei[N_EDGES + e];
    int p = atomicAdd(&cursor[d], 1);
    csr_src[p] = ei[e];
    pos[e] = p;
}

// ---------------- bond encoder -> CSR-ordered edge weights ----------------
__global__ void k_bond(const int* __restrict__ ea, const float* __restrict__ bemb,
                       const int* __restrict__ pos, float4* __restrict__ ewc) {
    int e = blockIdx.x * blockDim.x + threadIdx.x;
    if (e >= N_EDGES) return;
    int a0 = ea[e * 3 + 0], a1 = ea[e * 3 + 1], a2 = ea[e * 3 + 2];
    int p = pos[e];
#pragma unroll
    for (int l = 0; l < N_LAYERS; l++) {
        const float* b0 = bemb + (((l * BOND_FEATS + 0) * BOND_VOCAB + a0) * BOND_DIM);
        const float* b1 = bemb + (((l * BOND_FEATS + 1) * BOND_VOCAB + a1) * BOND_DIM);
        const float* b2 = bemb + (((l * BOND_FEATS + 2) * BOND_VOCAB + a2) * BOND_DIM);
        float4 w;
        w.x = b0[0] + b1[0] + b2[0];
        w.y = b0[1] + b1[1] + b2[1];
        w.z = b0[2] + b1[2] + b2[2];
        w.w = 0.f;
        ewc[(size_t)l * N_EDGES + p] = w;
    }
}

// ---------------- W -> fp16: WT[l][j][k*128+i] = W[l][k][i][j] ----------------
__global__ void k_prepW(const float* __restrict__ W, __half* __restrict__ WT) {
    int bl = blockIdx.x;                  // l*128 + j
    int l = bl >> 7, j = bl & 127;
    int t = threadIdx.x;                  // 384: k*128+i
    int k = t >> 7, i = t & 127;
    WT[(size_t)bl * 384 + t] =
        __float2half(W[(((size_t)(l * BOND_DIM + k)) * EMB + i) * EMB + j]);
}

// ---------------- aggregation: z_k[d] = sum_e ew[e,k] * hh[src_e] ----------------
__global__ void __launch_bounds__(256)
k_aggz(const int* __restrict__ start, const int* __restrict__ csr_src,
       const float4* __restrict__ ewc, const __half* __restrict__ hh,
       __half* __restrict__ z) {
    int w = threadIdx.x >> 5;
    int lane = threadIdx.x & 31;
    int d = blockIdx.x * 8 + w;
    if (d >= N_NODES) return;
    int s = start[d], e = start[d + 1];
    float a0[4] = {0, 0, 0, 0}, a1[4] = {0, 0, 0, 0}, a2[4] = {0, 0, 0, 0};
    for (int j = s; j < e; j++) {
        int src = __ldg(&csr_src[j]);
        float4 wv = __ldg(&ewc[j]);
        uint2 u = __ldg((const uint2*)(hh + (size_t)src * EMB + lane * 4));
        float2 p0 = __half22float2(*(const half2*)&u.x);
        float2 p1 = __half22float2(*(const half2*)&u.y);
        float hv0 = p0.x, hv1 = p0.y, hv2 = p1.x, hv3 = p1.y;
        a0[0] += wv.x * hv0; a0[1] += wv.x * hv1; a0[2] += wv.x * hv2; a0[3] += wv.x * hv3;
        a1[0] += wv.y * hv0; a1[1] += wv.y * hv1; a1[2] += wv.y * hv2; a1[3] += wv.y * hv3;
        a2[0] += wv.z * hv0; a2[1] += wv.z * hv1; a2[2] += wv.z * hv2; a2[3] += wv.z * hv3;
    }
    __half* zd = z + (size_t)d * 384 + lane * 4;
    *(half2*)(zd + 0)       = __floats2half2_rn(a0[0], a0[1]);
    *(half2*)(zd + 2)       = __floats2half2_rn(a0[2], a0[3]);
    *(half2*)(zd + 128)     = __floats2half2_rn(a1[0], a1[1]);
    *(half2*)(zd + 130)     = __floats2half2_rn(a1[2], a1[3]);
    *(half2*)(zd + 256)     = __floats2half2_rn(a2[0], a2[1]);
    *(half2*)(zd + 258)     = __floats2half2_rn(a2[2], a2[3]);
}

// ---------------- fused GEMM + update: h = act(Z@Wcat + bias) + h ----------------
// Block: 128(M) x 128(N), K=384 in 3 resident chunks. 8 warps (4m x 2n), warp 32x64.
#define LDA 136

__global__ void __launch_bounds__(256, 2)
k_gemm_fused(const __half* __restrict__ Z, const __half* __restrict__ WT,
             const float* __restrict__ bl, float* __restrict__ h,
             __half* __restrict__ hh, int relu) {
    extern __shared__ __half sm[];
    __half* As = sm;                    // [128][LDA]
    __half* Bs = sm + 128 * LDA;        // [128][LDA]
    float* sbias = (float*)(sm + 2 * 128 * LDA);   // [128]
    const int M = N_NODES;
    int tid = threadIdx.x;
    int m0 = blockIdx.x * 128;

    if (tid < 128) sbias[tid] = bl[tid] + bl[EMB + tid] + bl[2 * EMB + tid];

    int wid = tid >> 5, lane = tid & 31;
    int wm = wid & 3, wn = wid >> 2;
    int mbase = wm * 32, nbase = wn * 64;

    float acc[2][8][4];
#pragma unroll
    for (int i = 0; i < 2; i++)
#pragma unroll
        for (int j = 0; j < 8; j++)
#pragma unroll
            for (int q = 0; q < 4; q++) acc[i][j][q] = 0.f;

    for (int kc = 0; kc < 384; kc += 128) {
        __syncthreads();
        // A tile: 128 rows x 128 halves of Z (stride 384)
#pragma unroll
        for (int r = 0; r < 8; r++) {
            int lin = tid + r * 256;
            int row = lin >> 4;
            int col = (lin & 15) << 3;
            uint4 v = make_uint4(0u, 0u, 0u, 0u);
            int gm = m0 + row;
            if (gm < M) v = *(const uint4*)(Z + (size_t)gm * 384 + kc + col);
            *(uint4*)(As + row * LDA + col) = v;
        }
        // B tile: 128 n-rows x 128 k-halves of WT (stride 384)
#pragma unroll
        for (int r = 0; r < 8; r++) {
            int lin = tid + r * 256;
            int row = lin >> 4;
            int col = (lin & 15) << 3;
            uint4 v = *(const uint4*)(WT + (size_t)row * 384 + kc + col);
            *(uint4*)(Bs + row * LDA + col) = v;
        }
        __syncthreads();

#pragma unroll
        for (int k16 = 0; k16 < 8; k16++) {
            int kk = k16 * 16;
            uint32_t a[2][4];
#pragma unroll
            for (int i = 0; i < 2; i++) {
                int row = mbase + i * 16 + (lane & 15);
                int col = kk + (lane >> 4) * 8;
                uint32_t addr = smem_u32(As + row * LDA + col);
                asm volatile("ldmatrix.sync.aligned.m8n8.x4.shared.b16 {%0,%1,%2,%3}, [%4];"
                             : "=r"(a[i][0]), "=r"(a[i][1]), "=r"(a[i][2]), "=r"(a[i][3])
                             : "r"(addr));
            }
            uint32_t bf[4][4];
#pragma unroll
            for (int j = 0; j < 4; j++) {
                int nrow = nbase + j * 16 + ((lane >> 4) << 3) + (lane & 7);
                int col = kk + (((lane >> 3) & 1) << 3);
                uint32_t addr = smem_u32(Bs + nrow * LDA + col);
                asm volatile("ldmatrix.sync.aligned.m8n8.x4.shared.b16 {%0,%1,%2,%3}, [%4];"
                             : "=r"(bf[j][0]), "=r"(bf[j][1]), "=r"(bf[j][2]), "=r"(bf[j][3])
                             : "r"(addr));
            }
#pragma unroll
            for (int i = 0; i < 2; i++) {
#pragma unroll
                for (int jj = 0; jj < 8; jj++) {
                    uint32_t b0 = bf[jj >> 1][(jj & 1) * 2 + 0];
                    uint32_t b1 = bf[jj >> 1][(jj & 1) * 2 + 1];
                    asm volatile(
                        "mma.sync.aligned.m16n8k16.row.col.f32.f16.f16.f32 "
                        "{%0,%1,%2,%3}, {%4,%5,%6,%7}, {%8,%9}, {%0,%1,%2,%3};"
                        : "+f"(acc[i][jj][0]), "+f"(acc[i][jj][1]),
                          "+f"(acc[i][jj][2]), "+f"(acc[i][jj][3])
                        : "r"(a[i][0]), "r"(a[i][1]), "r"(a[i][2]), "r"(a[i][3]),
                          "r"(b0), "r"(b1));
                }
            }
        }
    }

    // epilogue: v = act(acc + bias); h = v + h_old; hh = half(h)
#pragma unroll
    for (int i = 0; i < 2; i++) {
        int row0 = m0 + mbase + i * 16 + (lane >> 2);
#pragma unroll
        for (int jj = 0; jj < 8; jj++) {
            int col = nbase + jj * 8 + 2 * (lane & 3);
            float b0 = sbias[col], b1 = sbias[col + 1];
#pragma unroll
            for (int half_row = 0; half_row < 2; half_row++) {
                int row = row0 + half_row * 8;
                if (row >= M) continue;
                float v0 = acc[i][jj][half_row * 2 + 0] + b0;
                float v1 = acc[i][jj][half_row * 2 + 1] + b1;
                if (relu) { v0 = fmaxf(v0, 0.f); v1 = fmaxf(v1, 0.f); }
                size_t idx = (size_t)row * EMB + col;
                float2 ho = *(float2*)(h + idx);
                float n0 = v0 + ho.x, n1 = v1 + ho.y;
                *(float2*)(h + idx) = make_float2(n0, n1);
                *(half2*)(hh + idx) = __floats2half2_rn(n0, n1);
            }
        }
    }
}

// ---------------- pooling ----------------
__global__ void k_pool(const int* __restrict__ batch, const float* __restrict__ h,
                       float* __restrict__ gsum, float* __restrict__ gcnt) {
    int n = blockIdx.x;
    int t = threadIdx.x;
    int g = __ldg(&batch[n]);
    atomicAdd(&gsum[(size_t)g * EMB + t], h[(size_t)n * EMB + t]);
    if (t == 0) atomicAdd(&gcnt[g], 1.0f);
}

// ---------------- final FCs ----------------
__global__ void k_final(const float* __restrict__ gsum, const float* __restrict__ gcnt,
                        const float* __restrict__ fc1_w, const float* __restrict__ fc1_b,
                        const float* __restrict__ fc2_w, const float* __restrict__ fc2_b,
                        float* __restrict__ out) {
    int g = blockIdx.x;
    int t = threadIdx.x;
    __shared__ float hg[EMB];
    __shared__ float red[EMB];
    float cnt = fmaxf(gcnt[g], 1.0f);
    hg[t] = gsum[(size_t)g * EMB + t] / cnt;
    __syncthreads();
    float z = fc1_b[t];
#pragma unroll 8
    for (int i = 0; i < EMB; i++) z += hg[i] * fc1_w[i * EMB + t];
    red[t] = z * fc2_w[t];
    __syncthreads();
    for (int s = 64; s > 0; s >>= 1) {
        if (t < s) red[t] += red[t + s];
        __syncthreads();
    }
    if (t == 0) out[g] = red[0] + fc2_b[0];
}

extern "C" void kernel_launch(void* const* d_in, const int* in_sizes, int n_in,
                              void* d_out, int out_size) {
    const int*   x     = (const int*)d_in[0];
    const int*   ei    = (const int*)d_in[1];
    const int*   ea    = (const int*)d_in[2];
    const int*   batch = (const int*)d_in[3];
    const float* aemb  = (const float*)d_in[4];
    const float* bemb  = (const float*)d_in[5];
    const float* W     = (const float*)d_in[6];
    const float* b     = (const float*)d_in[7];
    const float* fc1_w = (const float*)d_in[8];
    const float* fc1_b = (const float*)d_in[9];
    const float* fc2_w = (const float*)d_in[10];
    const float* fc2_b = (const float*)d_in[11];
    float* out = (float*)d_out;

    float *h, *gsum, *gcnt;
    __half *hh, *Z, *WT;
    float4* ewc;
    int *cnt, *start, *cursor, *csr_src, *pos;
    cudaGetSymbolAddress((void**)&h, g_h);
    cudaGetSymbolAddress((void**)&hh, g_hh);
    cudaGetSymbolAddress((void**)&Z, g_Z);
    cudaGetSymbolAddress((void**)&ewc, g_ewc);
    cudaGetSymbolAddress((void**)&WT, g_WT);
    cudaGetSymbolAddress((void**)&gsum, g_gsum);
    cudaGetSymbolAddress((void**)&gcnt, g_gcnt);
    cudaGetSymbolAddress((void**)&cnt, g_cnt);
    cudaGetSymbolAddress((void**)&start, g_start);
    cudaGetSymbolAddress((void**)&cursor, g_cursor);
    cudaGetSymbolAddress((void**)&csr_src, g_csr_src);
    cudaGetSymbolAddress((void**)&pos, g_pos);

    const int smem_bytes = 2 * 128 * LDA * sizeof(__half) + 128 * sizeof(float); // 70144
    cudaFuncSetAttribute(k_gemm_fused, cudaFuncAttributeMaxDynamicSharedMemorySize, smem_bytes);

    // CSR build
    cudaMemsetAsync(cnt, 0, N_NODES * sizeof(int));
    k_count<<<(N_EDGES + 255) / 256, 256>>>(ei, cnt);
    k_scan<<<1, 1024>>>(cnt, start, cursor);
    k_place<<<(N_EDGES + 255) / 256, 256>>>(ei, cursor, csr_src, pos);

    k_atom<<<N_NODES, EMB>>>(x, aemb, h, hh);
    k_bond<<<(N_EDGES + 255) / 256, 256>>>(ea, bemb, pos, ewc);
    k_prepW<<<N_LAYERS * EMB, 3 * EMB>>>(W, WT);

    for (int layer = 0; layer < N_LAYERS; layer++) {
        k_aggz<<<(N_NODES + 7) / 8, 256>>>(start, csr_src,
                                           ewc + (size_t)layer * N_EDGES, hh, Z);
        k_gemm_fused<<<(N_NODES + 127) / 128, 256, smem_bytes>>>(
            Z, WT + (size_t)layer * EMB * 384, b + (size_t)layer * BOND_DIM * EMB,
            h, hh, layer < N_LAYERS - 1 ? 1 : 0);
    }

    cudaMemsetAsync(gsum, 0, (size_t)N_GRAPHS * EMB * sizeof(float));
    cudaMemsetAsync(gcnt, 0, (size_t)N_GRAPHS * sizeof(float));
    k_pool<<<N_NODES, EMB>>>(batch, h, gsum, gcnt);
    k_final<<<N_GRAPHS, EMB>>>(gsum, gcnt, fc1_w, fc1_b, fc2_w, fc2_b, out);
}

// round 5
// speedup vs baseline: 2.1702x; 1.0537x over previous
#include <cuda_runtime.h>
#include <cuda_fp16.h>
#include <cuda_bf16.h>
#include <cstdint>

#define N_NODES 50000
#define N_EDGES 600000
#define N_GRAPHS 2048
#define EMB 128
#define N_LAYERS 3
#define ATOM_FEATS 9
#define ATOM_VOCAB 100
#define BOND_FEATS 3
#define BOND_VOCAB 8
#define BOND_DIM 3

// ---------------- scratch ----------------
__device__ float  g_h[N_NODES * EMB];              // fp32 master h
__device__ __half g_hh[N_NODES * EMB];             // fp16 copy for gather/MMA
__device__ __half g_Z[(size_t)N_NODES * 3 * EMB];  // fp16 aggregated features
__device__ float4 g_ewc[N_LAYERS * N_EDGES];       // edge weights in CSR order
__device__ __half g_WT[N_LAYERS * EMB * 3 * EMB];  // WT[l][j][k*128+i] = W[l][k][i][j]
__device__ float  g_gsum[N_GRAPHS * EMB];
__device__ float  g_gcnt[N_GRAPHS];
// CSR
__device__ int    g_cnt[N_NODES];
__device__ int    g_start[N_NODES + 1];
__device__ int    g_cursor[N_NODES];
__device__ int    g_csr_src[N_EDGES];
__device__ int    g_pos[N_EDGES];

__device__ __forceinline__ uint32_t smem_u32(const void* p) {
    uint32_t a;
    asm("{ .reg .u64 t; cvta.to.shared.u64 t, %1; cvt.u32.u64 %0, t; }" : "=r"(a) : "l"(p));
    return a;
}

// ---------------- atom encoder: warp per node ----------------
__global__ void __launch_bounds__(256)
k_atom(const int* __restrict__ x, const float* __restrict__ aemb,
       float* __restrict__ h, __half* __restrict__ hh) {
    int n = blockIdx.x * 8 + (threadIdx.x >> 5);
    if (n >= N_NODES) return;
    int lane = threadIdx.x & 31;
    int xv = 0;
    if (lane < ATOM_FEATS) xv = __ldg(&x[n * ATOM_FEATS + lane]);
    float4 s = make_float4(0.f, 0.f, 0.f, 0.f);
#pragma unroll
    for (int c = 0; c < ATOM_FEATS; c++) {
        int xc = __shfl_sync(0xffffffffu, xv, c);
        float4 v = *(const float4*)(aemb + ((size_t)(c * ATOM_VOCAB + xc)) * EMB + lane * 4);
        s.x += v.x; s.y += v.y; s.z += v.z; s.w += v.w;
    }
    size_t idx = (size_t)n * EMB + lane * 4;
    *(float4*)(h + idx) = s;
    half2 h0 = __floats2half2_rn(s.x, s.y);
    half2 h1 = __floats2half2_rn(s.z, s.w);
    *(half2*)(hh + idx) = h0;
    *(half2*)(hh + idx + 2) = h1;
}

// ---------------- CSR build ----------------
__global__ void k_count(const int* __restrict__ ei, int* __restrict__ cnt) {
    int e = blockIdx.x * blockDim.x + threadIdx.x;
    if (e < N_EDGES) atomicAdd(&cnt[ei[N_EDGES + e]], 1);
}

__global__ void k_gcnt(const int* __restrict__ batch, float* __restrict__ gcnt) {
    int n = blockIdx.x * blockDim.x + threadIdx.x;
    if (n < N_NODES) atomicAdd(&gcnt[batch[n]], 1.0f);
}

__global__ void k_scan(const int* __restrict__ cnt, int* __restrict__ start,
                       int* __restrict__ cursor) {
    __shared__ int ssum[1024];
    int t = threadIdx.x;
    const int PER = 49;
    int lo = t * PER;
    int s = 0;
    for (int i = 0; i < PER; i++) {
        int idx = lo + i;
        if (idx < N_NODES) s += cnt[idx];
    }
    ssum[t] = s;
    __syncthreads();
    for (int off = 1; off < 1024; off <<= 1) {
        int v = (t >= off) ? ssum[t - off] : 0;
        __syncthreads();
        ssum[t] += v;
        __syncthreads();
    }
    int run = ssum[t] - s;
    for (int i = 0; i < PER; i++) {
        int idx = lo + i;
        if (idx < N_NODES) {
            start[idx] = run;
            cursor[idx] = run;
            run += cnt[idx];
        }
    }
    if (t == 0) start[N_NODES] = N_EDGES;
}

__global__ void k_place(const int* __restrict__ ei, int* __restrict__ cursor,
                        int* __restrict__ csr_src, int* __restrict__ pos) {
    int e = blockIdx.x * blockDim.x + threadIdx.x;
    if (e >= N_EDGES) return;
    int d = ei[N_EDGES + e];
    int p = atomicAdd(&cursor[d], 1);
    csr_src[p] = ei[e];
    pos[e] = p;
}

// ---------------- bond encoder -> CSR-ordered edge weights ----------------
__global__ void k_bond(const int* __restrict__ ea, const float* __restrict__ bemb,
                       const int* __restrict__ pos, float4* __restrict__ ewc) {
    int e = blockIdx.x * blockDim.x + threadIdx.x;
    if (e >= N_EDGES) return;
    int a0 = ea[e * 3 + 0], a1 = ea[e * 3 + 1], a2 = ea[e * 3 + 2];
    int p = pos[e];
#pragma unroll
    for (int l = 0; l < N_LAYERS; l++) {
        const float* b0 = bemb + (((l * BOND_FEATS + 0) * BOND_VOCAB + a0) * BOND_DIM);
        const float* b1 = bemb + (((l * BOND_FEATS + 1) * BOND_VOCAB + a1) * BOND_DIM);
        const float* b2 = bemb + (((l * BOND_FEATS + 2) * BOND_VOCAB + a2) * BOND_DIM);
        float4 w;
        w.x = b0[0] + b1[0] + b2[0];
        w.y = b0[1] + b1[1] + b2[1];
        w.z = b0[2] + b1[2] + b2[2];
        w.w = 0.f;
        ewc[(size_t)l * N_EDGES + p] = w;
    }
}

// ---------------- W -> fp16: WT[l][j][k*128+i] = W[l][k][i][j] ----------------
__global__ void k_prepW(const float* __restrict__ W, __half* __restrict__ WT) {
    int bl = blockIdx.x;
    int l = bl >> 7, j = bl & 127;
    int t = threadIdx.x;
    int k = t >> 7, i = t & 127;
    WT[(size_t)bl * 384 + t] =
        __float2half(W[(((size_t)(l * BOND_DIM + k)) * EMB + i) * EMB + j]);
}

// ---------------- aggregation: z_k[d] = sum_e ew[e,k] * hh[src_e] (MLP-4) -------
__global__ void __launch_bounds__(256)
k_aggz(const int* __restrict__ start, const int* __restrict__ csr_src,
       const float4* __restrict__ ewc, const __half* __restrict__ hh,
       __half* __restrict__ z) {
    int w = threadIdx.x >> 5;
    int lane = threadIdx.x & 31;
    int d = blockIdx.x * 8 + w;
    if (d >= N_NODES) return;
    int s = start[d], e = start[d + 1];
    float a0[4] = {0, 0, 0, 0}, a1[4] = {0, 0, 0, 0}, a2[4] = {0, 0, 0, 0};

    int j = s;
    for (; j + 4 <= e; j += 4) {
        int s0 = __ldg(&csr_src[j + 0]);
        int s1 = __ldg(&csr_src[j + 1]);
        int s2 = __ldg(&csr_src[j + 2]);
        int s3 = __ldg(&csr_src[j + 3]);
        float4 w0 = __ldg(&ewc[j + 0]);
        float4 w1 = __ldg(&ewc[j + 1]);
        float4 w2 = __ldg(&ewc[j + 2]);
        float4 w3 = __ldg(&ewc[j + 3]);
        uint2 u0 = __ldg((const uint2*)(hh + (size_t)s0 * EMB + lane * 4));
        uint2 u1 = __ldg((const uint2*)(hh + (size_t)s1 * EMB + lane * 4));
        uint2 u2 = __ldg((const uint2*)(hh + (size_t)s2 * EMB + lane * 4));
        uint2 u3 = __ldg((const uint2*)(hh + (size_t)s3 * EMB + lane * 4));
#define ACC(u, wv) do { \
        float2 p0 = __half22float2(*(const half2*)&(u).x); \
        float2 p1 = __half22float2(*(const half2*)&(u).y); \
        a0[0] += (wv).x * p0.x; a0[1] += (wv).x * p0.y; a0[2] += (wv).x * p1.x; a0[3] += (wv).x * p1.y; \
        a1[0] += (wv).y * p0.x; a1[1] += (wv).y * p0.y; a1[2] += (wv).y * p1.x; a1[3] += (wv).y * p1.y; \
        a2[0] += (wv).z * p0.x; a2[1] += (wv).z * p0.y; a2[2] += (wv).z * p1.x; a2[3] += (wv).z * p1.y; \
    } while (0)
        ACC(u0, w0); ACC(u1, w1); ACC(u2, w2); ACC(u3, w3);
    }
    for (; j < e; j++) {
        int src = __ldg(&csr_src[j]);
        float4 wv = __ldg(&ewc[j]);
        uint2 u = __ldg((const uint2*)(hh + (size_t)src * EMB + lane * 4));
        ACC(u, wv);
    }
#undef ACC
    __half* zd = z + (size_t)d * 384 + lane * 4;
    *(half2*)(zd + 0)   = __floats2half2_rn(a0[0], a0[1]);
    *(half2*)(zd + 2)   = __floats2half2_rn(a0[2], a0[3]);
    *(half2*)(zd + 128) = __floats2half2_rn(a1[0], a1[1]);
    *(half2*)(zd + 130) = __floats2half2_rn(a1[2], a1[3]);
    *(half2*)(zd + 256) = __floats2half2_rn(a2[0], a2[1]);
    *(half2*)(zd + 258) = __floats2half2_rn(a2[2], a2[3]);
}

// ---------------- fused GEMM + update (+ optional pooling on last layer) -------
#define LDA 136

__global__ void __launch_bounds__(256, 2)
k_gemm_fused(const __half* __restrict__ Z, const __half* __restrict__ WT,
             const float* __restrict__ bl, float* __restrict__ h,
             __half* __restrict__ hh, int relu,
             const int* __restrict__ batch, float* __restrict__ gsum, int do_pool) {
    extern __shared__ __half sm[];
    __half* As = sm;
    __half* Bs = sm + 128 * LDA;
    float* sbias = (float*)(sm + 2 * 128 * LDA);
    const int M = N_NODES;
    int tid = threadIdx.x;
    int m0 = blockIdx.x * 128;

    if (tid < 128) sbias[tid] = bl[tid] + bl[EMB + tid] + bl[2 * EMB + tid];

    int wid = tid >> 5, lane = tid & 31;
    int wm = wid & 3, wn = wid >> 2;
    int mbase = wm * 32, nbase = wn * 64;

    float acc[2][8][4];
#pragma unroll
    for (int i = 0; i < 2; i++)
#pragma unroll
        for (int j = 0; j < 8; j++)
#pragma unroll
            for (int q = 0; q < 4; q++) acc[i][j][q] = 0.f;

    for (int kc = 0; kc < 384; kc += 128) {
        __syncthreads();
#pragma unroll
        for (int r = 0; r < 8; r++) {
            int lin = tid + r * 256;
            int row = lin >> 4;
            int col = (lin & 15) << 3;
            uint4 v = make_uint4(0u, 0u, 0u, 0u);
            int gm = m0 + row;
            if (gm < M) v = *(const uint4*)(Z + (size_t)gm * 384 + kc + col);
            *(uint4*)(As + row * LDA + col) = v;
        }
#pragma unroll
        for (int r = 0; r < 8; r++) {
            int lin = tid + r * 256;
            int row = lin >> 4;
            int col = (lin & 15) << 3;
            uint4 v = *(const uint4*)(WT + (size_t)row * 384 + kc + col);
            *(uint4*)(Bs + row * LDA + col) = v;
        }
        __syncthreads();

#pragma unroll
        for (int k16 = 0; k16 < 8; k16++) {
            int kk = k16 * 16;
            uint32_t a[2][4];
#pragma unroll
            for (int i = 0; i < 2; i++) {
                int row = mbase + i * 16 + (lane & 15);
                int col = kk + (lane >> 4) * 8;
                uint32_t addr = smem_u32(As + row * LDA + col);
                asm volatile("ldmatrix.sync.aligned.m8n8.x4.shared.b16 {%0,%1,%2,%3}, [%4];"
                             : "=r"(a[i][0]), "=r"(a[i][1]), "=r"(a[i][2]), "=r"(a[i][3])
                             : "r"(addr));
            }
            uint32_t bf[4][4];
#pragma unroll
            for (int j = 0; j < 4; j++) {
                int nrow = nbase + j * 16 + ((lane >> 4) << 3) + (lane & 7);
                int col = kk + (((lane >> 3) & 1) << 3);
                uint32_t addr = smem_u32(Bs + nrow * LDA + col);
                asm volatile("ldmatrix.sync.aligned.m8n8.x4.shared.b16 {%0,%1,%2,%3}, [%4];"
                             : "=r"(bf[j][0]), "=r"(bf[j][1]), "=r"(bf[j][2]), "=r"(bf[j][3])
                             : "r"(addr));
            }
#pragma unroll
            for (int i = 0; i < 2; i++) {
#pragma unroll
                for (int jj = 0; jj < 8; jj++) {
                    uint32_t b0 = bf[jj >> 1][(jj & 1) * 2 + 0];
                    uint32_t b1 = bf[jj >> 1][(jj & 1) * 2 + 1];
                    asm volatile(
                        "mma.sync.aligned.m16n8k16.row.col.f32.f16.f16.f32 "
                        "{%0,%1,%2,%3}, {%4,%5,%6,%7}, {%8,%9}, {%0,%1,%2,%3};"
                        : "+f"(acc[i][jj][0]), "+f"(acc[i][jj][1]),
                          "+f"(acc[i][jj][2]), "+f"(acc[i][jj][3])
                        : "r"(a[i][0]), "r"(a[i][1]), "r"(a[i][2]), "r"(a[i][3]),
                          "r"(b0), "r"(b1));
                }
            }
        }
    }

#pragma unroll
    for (int i = 0; i < 2; i++) {
        int row0 = m0 + mbase + i * 16 + (lane >> 2);
#pragma unroll
        for (int jj = 0; jj < 8; jj++) {
            int col = nbase + jj * 8 + 2 * (lane & 3);
            float b0 = sbias[col], b1 = sbias[col + 1];
#pragma unroll
            for (int half_row = 0; half_row < 2; half_row++) {
                int row = row0 + half_row * 8;
                if (row >= M) continue;
                float v0 = acc[i][jj][half_row * 2 + 0] + b0;
                float v1 = acc[i][jj][half_row * 2 + 1] + b1;
                if (relu) { v0 = fmaxf(v0, 0.f); v1 = fmaxf(v1, 0.f); }
                size_t idx = (size_t)row * EMB + col;
                float2 ho = *(float2*)(h + idx);
                float n0 = v0 + ho.x, n1 = v1 + ho.y;
                if (do_pool) {
                    int g = __ldg(&batch[row]);
                    float* gp = gsum + (size_t)g * EMB + col;
                    asm volatile("red.global.add.v2.f32 [%0], {%1, %2};"
                                 :: "l"(gp), "f"(n0), "f"(n1) : "memory");
                } else {
                    *(float2*)(h + idx) = make_float2(n0, n1);
                    *(half2*)(hh + idx) = __floats2half2_rn(n0, n1);
                }
            }
        }
    }
}

// ---------------- final FCs ----------------
__global__ void k_final(const float* __restrict__ gsum, const float* __restrict__ gcnt,
                        const float* __restrict__ fc1_w, const float* __restrict__ fc1_b,
                        const float* __restrict__ fc2_w, const float* __restrict__ fc2_b,
                        float* __restrict__ out) {
    int g = blockIdx.x;
    int t = threadIdx.x;
    __shared__ float hg[EMB];
    __shared__ float red[EMB];
    float cnt = fmaxf(gcnt[g], 1.0f);
    hg[t] = gsum[(size_t)g * EMB + t] / cnt;
    __syncthreads();
    float z = fc1_b[t];
#pragma unroll 8
    for (int i = 0; i < EMB; i++) z += hg[i] * fc1_w[i * EMB + t];
    red[t] = z * fc2_w[t];
    __syncthreads();
    for (int s = 64; s > 0; s >>= 1) {
        if (t < s) red[t] += red[t + s];
        __syncthreads();
    }
    if (t == 0) out[g] = red[0] + fc2_b[0];
}

extern "C" void kernel_launch(void* const* d_in, const int* in_sizes, int n_in,
                              void* d_out, int out_size) {
    const int*   x     = (const int*)d_in[0];
    const int*   ei    = (const int*)d_in[1];
    const int*   ea    = (const int*)d_in[2];
    const int*   batch = (const int*)d_in[3];
    const float* aemb  = (const float*)d_in[4];
    const float* bemb  = (const float*)d_in[5];
    const float* W     = (const float*)d_in[6];
    const float* b     = (const float*)d_in[7];
    const float* fc1_w = (const float*)d_in[8];
    const float* fc1_b = (const float*)d_in[9];
    const float* fc2_w = (const float*)d_in[10];
    const float* fc2_b = (const float*)d_in[11];
    float* out = (float*)d_out;

    float *h, *gsum, *gcnt;
    __half *hh, *Z, *WT;
    float4* ewc;
    int *cnt, *start, *cursor, *csr_src, *pos;
    cudaGetSymbolAddress((void**)&h, g_h);
    cudaGetSymbolAddress((void**)&hh, g_hh);
    cudaGetSymbolAddress((void**)&Z, g_Z);
    cudaGetSymbolAddress((void**)&ewc, g_ewc);
    cudaGetSymbolAddress((void**)&WT, g_WT);
    cudaGetSymbolAddress((void**)&gsum, g_gsum);
    cudaGetSymbolAddress((void**)&gcnt, g_gcnt);
    cudaGetSymbolAddress((void**)&cnt, g_cnt);
    cudaGetSymbolAddress((void**)&start, g_start);
    cudaGetSymbolAddress((void**)&cursor, g_cursor);
    cudaGetSymbolAddress((void**)&csr_src, g_csr_src);
    cudaGetSymbolAddress((void**)&pos, g_pos);

    const int smem_bytes = 2 * 128 * LDA * sizeof(__half) + 128 * sizeof(float);
    cudaFuncSetAttribute(k_gemm_fused, cudaFuncAttributeMaxDynamicSharedMemorySize, smem_bytes);

    // setup (CSR, counts, embeddings, weights)
    cudaMemsetAsync(cnt, 0, N_NODES * sizeof(int));
    cudaMemsetAsync(gsum, 0, (size_t)N_GRAPHS * EMB * sizeof(float));
    cudaMemsetAsync(gcnt, 0, (size_t)N_GRAPHS * sizeof(float));
    k_count<<<(N_EDGES + 255) / 256, 256>>>(ei, cnt);
    k_gcnt<<<(N_NODES + 255) / 256, 256>>>(batch, gcnt);
    k_scan<<<1, 1024>>>(cnt, start, cursor);
    k_place<<<(N_EDGES + 255) / 256, 256>>>(ei, cursor, csr_src, pos);

    k_atom<<<(N_NODES + 7) / 8, 256>>>(x, aemb, h, hh);
    k_bond<<<(N_EDGES + 255) / 256, 256>>>(ea, bemb, pos, ewc);
    k_prepW<<<N_LAYERS * EMB, 3 * EMB>>>(W, WT);

    for (int layer = 0; layer < N_LAYERS; layer++) {
        int last = (layer == N_LAYERS - 1);
        k_aggz<<<(N_NODES + 7) / 8, 256>>>(start, csr_src,
                                           ewc + (size_t)layer * N_EDGES, hh, Z);
        k_gemm_fused<<<(N_NODES + 127) / 128, 256, smem_bytes>>>(
            Z, WT + (size_t)layer * EMB * 384, b + (size_t)layer * BOND_DIM * EMB,
            h, hh, layer < N_LAYERS - 1 ? 1 : 0,
            batch, gsum, last);
    }

    k_final<<<N_GRAPHS, EMB>>>(gsum, gcnt, fc1_w, fc1_b, fc2_w, fc2_b, out);
}

// round 6
// speedup vs baseline: 2.3422x; 1.0793x over previous
#include <cuda_runtime.h>
#include <cuda_fp16.h>
#include <cuda_bf16.h>
#include <cstdint>

#define N_NODES 50000
#define N_EDGES 600000
#define N_GRAPHS 2048
#define EMB 128
#define N_LAYERS 3
#define ATOM_FEATS 9
#define ATOM_VOCAB 100
#define BOND_FEATS 3
#define BOND_VOCAB 8
#define BOND_DIM 3

#define CNT_PAD 53248   // 1024 threads * 52 (13 int4) >= N_NODES

// ---------------- scratch ----------------
__device__ float  g_h[N_NODES * EMB];
__device__ __half g_hh[N_NODES * EMB];
__device__ __half g_Z[(size_t)N_NODES * 3 * EMB];
__device__ float4 g_ewc[N_LAYERS * N_EDGES];
__device__ __half g_WT[N_LAYERS * EMB * 3 * EMB];
__device__ float  g_gsum[N_GRAPHS * EMB];
__device__ float  g_gcnt[N_GRAPHS];
__device__ int    g_cnt[CNT_PAD];
__device__ int    g_start[N_NODES + 1];
__device__ int    g_cursor[N_NODES];
__device__ int    g_csr_src[N_EDGES];

__device__ __forceinline__ uint32_t smem_u32(const void* p) {
    uint32_t a;
    asm("{ .reg .u64 t; cvta.to.shared.u64 t, %1; cvt.u32.u64 %0, t; }" : "=r"(a) : "l"(p));
    return a;
}

// ---------------- atom encoder: warp per node ----------------
__global__ void __launch_bounds__(256)
k_atom(const int* __restrict__ x, const float* __restrict__ aemb,
       float* __restrict__ h, __half* __restrict__ hh) {
    int n = blockIdx.x * 8 + (threadIdx.x >> 5);
    if (n >= N_NODES) return;
    int lane = threadIdx.x & 31;
    int xv = 0;
    if (lane < ATOM_FEATS) xv = __ldg(&x[n * ATOM_FEATS + lane]);
    float4 s = make_float4(0.f, 0.f, 0.f, 0.f);
#pragma unroll
    for (int c = 0; c < ATOM_FEATS; c++) {
        int xc = __shfl_sync(0xffffffffu, xv, c);
        float4 v = *(const float4*)(aemb + ((size_t)(c * ATOM_VOCAB + xc)) * EMB + lane * 4);
        s.x += v.x; s.y += v.y; s.z += v.z; s.w += v.w;
    }
    size_t idx = (size_t)n * EMB + lane * 4;
    *(float4*)(h + idx) = s;
    *(half2*)(hh + idx) = __floats2half2_rn(s.x, s.y);
    *(half2*)(hh + idx + 2) = __floats2half2_rn(s.z, s.w);
}

// ---------------- count (dst degrees) + graph counts, fused ----------------
__global__ void k_count(const int* __restrict__ ei, int* __restrict__ cnt,
                        const int* __restrict__ batch, float* __restrict__ gcnt) {
    int i = blockIdx.x * blockDim.x + threadIdx.x;
    if (i < N_EDGES) atomicAdd(&cnt[ei[N_EDGES + i]], 1);
    if (i < N_NODES) atomicAdd(&gcnt[batch[i]], 1.0f);
}

// ---------------- scan (single block, vectorized loads) ----------------
__global__ void __launch_bounds__(1024)
k_scan(const int4* __restrict__ cnt4, int* __restrict__ start, int* __restrict__ cursor) {
    __shared__ int ssum[1024];
    int t = threadIdx.x;
    int vals[52];
    int s = 0;
#pragma unroll
    for (int i = 0; i < 13; i++) {
        int4 v = __ldg(&cnt4[t * 13 + i]);
        vals[i * 4 + 0] = v.x; vals[i * 4 + 1] = v.y;
        vals[i * 4 + 2] = v.z; vals[i * 4 + 3] = v.w;
        s += v.x + v.y + v.z + v.w;
    }
    ssum[t] = s;
    __syncthreads();
    for (int off = 1; off < 1024; off <<= 1) {
        int v = (t >= off) ? ssum[t - off] : 0;
        __syncthreads();
        ssum[t] += v;
        __syncthreads();
    }
    int run = ssum[t] - s;
#pragma unroll
    for (int i = 0; i < 52; i++) {
        int idx = t * 52 + i;
        if (idx < N_NODES) {
            start[idx] = run;
            cursor[idx] = run;
            run += vals[i];
        }
    }
    if (t == 0) start[N_NODES] = N_EDGES;
}

// ---------------- place + bond encoder fused: CSR-ordered edge weights -------
__global__ void k_place_bond(const int* __restrict__ ei, const int* __restrict__ ea,
                             const float* __restrict__ bemb, int* __restrict__ cursor,
                             int* __restrict__ csr_src, float4* __restrict__ ewc) {
    int e = blockIdx.x * blockDim.x + threadIdx.x;
    if (e >= N_EDGES) return;
    int d = ei[N_EDGES + e];
    int p = atomicAdd(&cursor[d], 1);
    csr_src[p] = ei[e];
    int a0 = ea[e * 3 + 0], a1 = ea[e * 3 + 1], a2 = ea[e * 3 + 2];
#pragma unroll
    for (int l = 0; l < N_LAYERS; l++) {
        const float* b0 = bemb + (((l * BOND_FEATS + 0) * BOND_VOCAB + a0) * BOND_DIM);
        const float* b1 = bemb + (((l * BOND_FEATS + 1) * BOND_VOCAB + a1) * BOND_DIM);
        const float* b2 = bemb + (((l * BOND_FEATS + 2) * BOND_VOCAB + a2) * BOND_DIM);
        float4 w;
        w.x = b0[0] + b1[0] + b2[0];
        w.y = b0[1] + b1[1] + b2[1];
        w.z = b0[2] + b1[2] + b2[2];
        w.w = 0.f;
        ewc[(size_t)l * N_EDGES + p] = w;
    }
}

// ---------------- W -> fp16: WT[l][j][k*128+i] = W[l][k][i][j] ----------------
__global__ void k_prepW(const float* __restrict__ W, __half* __restrict__ WT) {
    int bl = blockIdx.x;
    int l = bl >> 7, j = bl & 127;
    int t = threadIdx.x;
    int k = t >> 7, i = t & 127;
    WT[(size_t)bl * 384 + t] =
        __float2half(W[(((size_t)(l * BOND_DIM + k)) * EMB + i) * EMB + j]);
}

// ---------------- aggregation: 2 nodes/warp, 16 lanes x uint4, lockstep -------
__global__ void __launch_bounds__(256)
k_aggz(const int* __restrict__ start, const int* __restrict__ csr_src,
       const float4* __restrict__ ewc, const __half* __restrict__ hh,
       __half* __restrict__ z) {
    int lane = threadIdx.x & 31;
    int half_id = lane >> 4;
    int sub = lane & 15;
    int d = blockIdx.x * 16 + (threadIdx.x >> 5) * 2 + half_id;
    bool valid = d < N_NODES;
    int s = 0, e = 0;
    if (valid) { s = __ldg(&start[d]); e = __ldg(&start[d + 1]); }
    int len = e - s;
    int mx = max(len, __shfl_xor_sync(0xffffffffu, len, 16));

    float a0[8] = {0,0,0,0,0,0,0,0};
    float a1[8] = {0,0,0,0,0,0,0,0};
    float a2[8] = {0,0,0,0,0,0,0,0};
    int cl = (len > 0) ? (len - 1) : 0;

#define LOADG(i, jj) \
    int idx##i = s + min((jj) + i, cl); \
    float m##i = ((jj) + i < len) ? 1.f : 0.f; \
    int src##i = __ldg(&csr_src[idx##i]); \
    float4 w##i = __ldg(&ewc[idx##i]); \
    uint4 u##i = __ldg((const uint4*)(hh + (size_t)src##i * EMB + sub * 8));

#define ACC(i) do { \
    float wx = w##i.x * m##i, wy = w##i.y * m##i, wz = w##i.z * m##i; \
    float2 p0 = __half22float2(*(const half2*)&u##i.x); \
    float2 p1 = __half22float2(*(const half2*)&u##i.y); \
    float2 p2 = __half22float2(*(const half2*)&u##i.z); \
    float2 p3 = __half22float2(*(const half2*)&u##i.w); \
    float hv[8] = {p0.x, p0.y, p1.x, p1.y, p2.x, p2.y, p3.x, p3.y}; \
    _Pragma("unroll") for (int q = 0; q < 8; q++) { \
        a0[q] += wx * hv[q]; a1[q] += wy * hv[q]; a2[q] += wz * hv[q]; } \
    } while (0)

    for (int jj = 0; jj < mx; jj += 4) {
        LOADG(0, jj); LOADG(1, jj); LOADG(2, jj); LOADG(3, jj);
        ACC(0); ACC(1); ACC(2); ACC(3);
    }
#undef LOADG
#undef ACC

    if (valid) {
        __half* zd = z + (size_t)d * 384 + sub * 8;
        half2 o[4];
#pragma unroll
        for (int q = 0; q < 4; q++) o[q] = __floats2half2_rn(a0[2*q], a0[2*q+1]);
        *(uint4*)(zd) = *(uint4*)o;
#pragma unroll
        for (int q = 0; q < 4; q++) o[q] = __floats2half2_rn(a1[2*q], a1[2*q+1]);
        *(uint4*)(zd + 128) = *(uint4*)o;
#pragma unroll
        for (int q = 0; q < 4; q++) o[q] = __floats2half2_rn(a2[2*q], a2[2*q+1]);
        *(uint4*)(zd + 256) = *(uint4*)o;
    }
}

// ---------------- fused GEMM + update (+ pooling on last layer) ---------------
#define LDA 136

__global__ void __launch_bounds__(256, 2)
k_gemm_fused(const __half* __restrict__ Z, const __half* __restrict__ WT,
             const float* __restrict__ bl, float* __restrict__ h,
             __half* __restrict__ hh, int relu,
             const int* __restrict__ batch, float* __restrict__ gsum, int do_pool) {
    extern __shared__ __half sm[];
    __half* As = sm;
    __half* Bs = sm + 128 * LDA;
    float* sbias = (float*)(sm + 2 * 128 * LDA);
    const int M = N_NODES;
    int tid = threadIdx.x;
    int m0 = blockIdx.x * 128;

    if (tid < 128) sbias[tid] = bl[tid] + bl[EMB + tid] + bl[2 * EMB + tid];

    int wid = tid >> 5, lane = tid & 31;
    int wm = wid & 3, wn = wid >> 2;
    int mbase = wm * 32, nbase = wn * 64;

    float acc[2][8][4];
#pragma unroll
    for (int i = 0; i < 2; i++)
#pragma unroll
        for (int j = 0; j < 8; j++)
#pragma unroll
            for (int q = 0; q < 4; q++) acc[i][j][q] = 0.f;

    for (int kc = 0; kc < 384; kc += 128) {
        __syncthreads();
#pragma unroll
        for (int r = 0; r < 8; r++) {
            int lin = tid + r * 256;
            int row = lin >> 4;
            int col = (lin & 15) << 3;
            uint4 v = make_uint4(0u, 0u, 0u, 0u);
            int gm = m0 + row;
            if (gm < M) v = *(const uint4*)(Z + (size_t)gm * 384 + kc + col);
            *(uint4*)(As + row * LDA + col) = v;
        }
#pragma unroll
        for (int r = 0; r < 8; r++) {
            int lin = tid + r * 256;
            int row = lin >> 4;
            int col = (lin & 15) << 3;
            uint4 v = *(const uint4*)(WT + (size_t)row * 384 + kc + col);
            *(uint4*)(Bs + row * LDA + col) = v;
        }
        __syncthreads();

#pragma unroll
        for (int k16 = 0; k16 < 8; k16++) {
            int kk = k16 * 16;
            uint32_t a[2][4];
#pragma unroll
            for (int i = 0; i < 2; i++) {
                int row = mbase + i * 16 + (lane & 15);
                int col = kk + (lane >> 4) * 8;
                uint32_t addr = smem_u32(As + row * LDA + col);
                asm volatile("ldmatrix.sync.aligned.m8n8.x4.shared.b16 {%0,%1,%2,%3}, [%4];"
                             : "=r"(a[i][0]), "=r"(a[i][1]), "=r"(a[i][2]), "=r"(a[i][3])
                             : "r"(addr));
            }
            uint32_t bf[4][4];
#pragma unroll
            for (int j = 0; j < 4; j++) {
                int nrow = nbase + j * 16 + ((lane >> 4) << 3) + (lane & 7);
                int col = kk + (((lane >> 3) & 1) << 3);
                uint32_t addr = smem_u32(Bs + nrow * LDA + col);
                asm volatile("ldmatrix.sync.aligned.m8n8.x4.shared.b16 {%0,%1,%2,%3}, [%4];"
                             : "=r"(bf[j][0]), "=r"(bf[j][1]), "=r"(bf[j][2]), "=r"(bf[j][3])
                             : "r"(addr));
            }
#pragma unroll
            for (int i = 0; i < 2; i++) {
#pragma unroll
                for (int jj = 0; jj < 8; jj++) {
                    uint32_t b0 = bf[jj >> 1][(jj & 1) * 2 + 0];
                    uint32_t b1 = bf[jj >> 1][(jj & 1) * 2 + 1];
                    asm volatile(
                        "mma.sync.aligned.m16n8k16.row.col.f32.f16.f16.f32 "
                        "{%0,%1,%2,%3}, {%4,%5,%6,%7}, {%8,%9}, {%0,%1,%2,%3};"
                        : "+f"(acc[i][jj][0]), "+f"(acc[i][jj][1]),
                          "+f"(acc[i][jj][2]), "+f"(acc[i][jj][3])
                        : "r"(a[i][0]), "r"(a[i][1]), "r"(a[i][2]), "r"(a[i][3]),
                          "r"(b0), "r"(b1));
                }
            }
        }
    }

#pragma unroll
    for (int i = 0; i < 2; i++) {
        int row0 = m0 + mbase + i * 16 + (lane >> 2);
#pragma unroll
        for (int jj = 0; jj < 8; jj++) {
            int col = nbase + jj * 8 + 2 * (lane & 3);
            float b0 = sbias[col], b1 = sbias[col + 1];
#pragma unroll
            for (int half_row = 0; half_row < 2; half_row++) {
                int row = row0 + half_row * 8;
                if (row >= M) continue;
                float v0 = acc[i][jj][half_row * 2 + 0] + b0;
                float v1 = acc[i][jj][half_row * 2 + 1] + b1;
                if (relu) { v0 = fmaxf(v0, 0.f); v1 = fmaxf(v1, 0.f); }
                size_t idx = (size_t)row * EMB + col;
                float2 ho = *(float2*)(h + idx);
                float n0 = v0 + ho.x, n1 = v1 + ho.y;
                if (do_pool) {
                    int g = __ldg(&batch[row]);
                    float* gp = gsum + (size_t)g * EMB + col;
                    asm volatile("red.global.add.v2.f32 [%0], {%1, %2};"
                                 :: "l"(gp), "f"(n0), "f"(n1) : "memory");
                } else {
                    *(float2*)(h + idx) = make_float2(n0, n1);
                    *(half2*)(hh + idx) = __floats2half2_rn(n0, n1);
                }
            }
        }
    }
}

// ---------------- final FCs ----------------
__global__ void k_final(const float* __restrict__ gsum, const float* __restrict__ gcnt,
                        const float* __restrict__ fc1_w, const float* __restrict__ fc1_b,
                        const float* __restrict__ fc2_w, const float* __restrict__ fc2_b,
                        float* __restrict__ out) {
    int g = blockIdx.x;
    int t = threadIdx.x;
    __shared__ float hg[EMB];
    __shared__ float red[EMB];
    float cnt = fmaxf(gcnt[g], 1.0f);
    hg[t] = gsum[(size_t)g * EMB + t] / cnt;
    __syncthreads();
    float z = fc1_b[t];
#pragma unroll 8
    for (int i = 0; i < EMB; i++) z += hg[i] * fc1_w[i * EMB + t];
    red[t] = z * fc2_w[t];
    __syncthreads();
    for (int s = 64; s > 0; s >>= 1) {
        if (t < s) red[t] += red[t + s];
        __syncthreads();
    }
    if (t == 0) out[g] = red[0] + fc2_b[0];
}

extern "C" void kernel_launch(void* const* d_in, const int* in_sizes, int n_in,
                              void* d_out, int out_size) {
    const int*   x     = (const int*)d_in[0];
    const int*   ei    = (const int*)d_in[1];
    const int*   ea    = (const int*)d_in[2];
    const int*   batch = (const int*)d_in[3];
    const float* aemb  = (const float*)d_in[4];
    const float* bemb  = (const float*)d_in[5];
    const float* W     = (const float*)d_in[6];
    const float* b     = (const float*)d_in[7];
    const float* fc1_w = (const float*)d_in[8];
    const float* fc1_b = (const float*)d_in[9];
    const float* fc2_w = (const float*)d_in[10];
    const float* fc2_b = (const float*)d_in[11];
    float* out = (float*)d_out;

    float *h, *gsum, *gcnt;
    __half *hh, *Z, *WT;
    float4* ewc;
    int *cnt, *start, *cursor, *csr_src;
    cudaGetSymbolAddress((void**)&h, g_h);
    cudaGetSymbolAddress((void**)&hh, g_hh);
    cudaGetSymbolAddress((void**)&Z, g_Z);
    cudaGetSymbolAddress((void**)&ewc, g_ewc);
    cudaGetSymbolAddress((void**)&WT, g_WT);
    cudaGetSymbolAddress((void**)&gsum, g_gsum);
    cudaGetSymbolAddress((void**)&gcnt, g_gcnt);
    cudaGetSymbolAddress((void**)&cnt, g_cnt);
    cudaGetSymbolAddress((void**)&start, g_start);
    cudaGetSymbolAddress((void**)&cursor, g_cursor);
    cudaGetSymbolAddress((void**)&csr_src, g_csr_src);

    const int smem_bytes = 2 * 128 * LDA * sizeof(__half) + 128 * sizeof(float);
    cudaFuncSetAttribute(k_gemm_fused, cudaFuncAttributeMaxDynamicSharedMemorySize, smem_bytes);

    cudaMemsetAsync(cnt, 0, CNT_PAD * sizeof(int));
    cudaMemsetAsync(gsum, 0, (size_t)N_GRAPHS * EMB * sizeof(float));
    cudaMemsetAsync(gcnt, 0, (size_t)N_GRAPHS * sizeof(float));
    k_count<<<(N_EDGES + 255) / 256, 256>>>(ei, cnt, batch, gcnt);
    k_scan<<<1, 1024>>>((const int4*)cnt, start, cursor);
    k_place_bond<<<(N_EDGES + 255) / 256, 256>>>(ei, ea, bemb, cursor, csr_src, ewc);

    k_atom<<<(N_NODES + 7) / 8, 256>>>(x, aemb, h, hh);
    k_prepW<<<N_LAYERS * EMB, 3 * EMB>>>(W, WT);

    for (int layer = 0; layer < N_LAYERS; layer++) {
        int last = (layer == N_LAYERS - 1);
        k_aggz<<<(N_NODES + 15) / 16, 256>>>(start, csr_src,
                                             ewc + (size_t)layer * N_EDGES, hh, Z);
        k_gemm_fused<<<(N_NODES + 127) / 128, 256, smem_bytes>>>(
            Z, WT + (size_t)layer * EMB * 384, b + (size_t)layer * BOND_DIM * EMB,
            h, hh, layer < N_LAYERS - 1 ? 1 : 0,
            batch, gsum, last);
    }

    k_final<<<N_GRAPHS, EMB>>>(gsum, gcnt, fc1_w, fc1_b, fc2_w, fc2_b, out);
}